// round 10
// baseline (speedup 1.0000x reference)
#include <cuda_runtime.h>
#include <stdint.h>

#define TPB    256
#define NWARP  (TPB / 32)          // 8
#define NBLK   592                 // 4 CTAs/SM * 148 SMs
#define GW     (NBLK * NWARP)      // 4736 warps total
#define KTOP   16
#define CHPTS  64                  // points per warp-chunk
#define CHF4   96                  // float4 per chunk (64*6/4)

typedef unsigned long long u64;

__device__ u64 g_cand[NBLK * KTOP];
__device__ int g_done;             // zero at start; last block resets it

static __device__ __forceinline__ u64 make_key(float d2, int idx) {
    // d2 >= 0 -> float bits monotone. Larger key = larger d2; ties -> smaller
    // index (via ~idx), matching jax.lax.top_k ordering.
    return (((u64)__float_as_uint(d2)) << 32) | (unsigned)(~(unsigned)idx);
}

static __device__ __forceinline__ u64 umax64(u64 a, u64 b) { return a > b ? a : b; }

static __device__ __forceinline__ u64 warp_min16(u64 mykey, int lane) {
    u64 t = (lane < 16) ? mykey : 0xFFFFFFFFFFFFFFFFULL;
    #pragma unroll
    for (int off = 16; off; off >>= 1) {
        u64 o = __shfl_xor_sync(0xFFFFFFFFu, t, off);
        t = o < t ? o : t;
    }
    return t;
}

// Insert per-lane candidate kk into running top-16 (lanes 0..15 hold mykey).
// Warp-uniform control flow; full warp participates.
static __device__ __forceinline__ void warp_insert(u64 kk, u64& mykey,
                                                   u64& thresh, int lane) {
    const unsigned FULL = 0xFFFFFFFFu;
    unsigned bal = __ballot_sync(FULL, kk > thresh);
    while (bal) {
        int src = __ffs(bal) - 1;
        bal &= bal - 1;
        u64 ck = __shfl_sync(FULL, kk, src);
        if (ck > thresh) {   // warp-uniform recheck (thresh may have risen)
            unsigned who = __ballot_sync(FULL, (lane < 16) & (mykey == thresh));
            int ml = __ffs(who) - 1;
            if (lane == ml) mykey = ck;
            thresh = warp_min16(mykey, lane);
        }
    }
}

// Bitonic sort descending across lanes 0..15 (full warp executes).
static __device__ __forceinline__ u64 sort16_desc(u64 v, int lane) {
    #pragma unroll
    for (int k = 2; k <= 16; k <<= 1) {
        #pragma unroll
        for (int j = k >> 1; j > 0; j >>= 1) {
            u64 o = __shfl_xor_sync(0xFFFFFFFFu, v, j);
            bool up = ((lane & k) == 0);
            bool lower = ((lane & j) == 0);
            v = ((lower == up) ? (v > o) : (v < o)) ? v : o;
        }
    }
    return v;
}

// Bitonic clean (descending) in aligned 16-lane groups; input bitonic.
// MUST be executed by all 32 lanes (full-mask shfl inside).
static __device__ __forceinline__ u64 clean16_desc(u64 c, int id) {
    #pragma unroll
    for (int j = 8; j > 0; j >>= 1) {
        u64 o = __shfl_xor_sync(0xFFFFFFFFu, c, j);
        c = (((id & j) == 0) ? (c > o) : (c < o)) ? c : o;
    }
    return c;
}

__global__ void __launch_bounds__(TPB, 4)
locse_fused(const float* __restrict__ P, const float* __restrict__ W,
            const float* __restrict__ bb, const int* __restrict__ iptr,
            float* __restrict__ out, int n, int f4max, int niter) {
    const unsigned FULL = 0xFFFFFFFFu;
    // raw smem: tiles (8 warps x 2 bufs x 96 float4 = 24576 B) reused later as
    // merge scratch (296*16 u64 = 37888 B). Max = 37888.
    __shared__ __align__(16) char smem_raw[296 * KTOP * 8];
    const float4* __restrict__ P4 = (const float4*)P;
    int t = threadIdx.x, lane = t & 31, wid = t >> 5;
    int gw = blockIdx.x * NWARP + wid;        // global warp id

    float4* tile0 = (float4*)smem_raw + (wid * 2 + 0) * CHF4;
    float4* tile1 = (float4*)smem_raw + (wid * 2 + 1) * CHF4;

    int qi = *iptr;
    float pix = __ldg(P + (size_t)qi * 6 + 0);
    float piy = __ldg(P + (size_t)qi * 6 + 1);
    float piz = __ldg(P + (size_t)qi * 6 + 2);

    u64 mykey = 0ULL, thresh = 0ULL;

    // ---- prologue: load chunk(0) -> rA, chunk(1) -> rB; stage chunk(0) ----
    float4 rA0, rA1, rA2, rB0, rB1, rB2;
    {
        int c0 = gw, c1 = gw + GW;
        int b0 = 96 * c0, b1 = 96 * c1;
        rA0 = __ldg(P4 + min(b0 + lane,      f4max - 1));
        rA1 = __ldg(P4 + min(b0 + 32 + lane, f4max - 1));
        rA2 = __ldg(P4 + min(b0 + 64 + lane, f4max - 1));
        rB0 = __ldg(P4 + min(b1 + lane,      f4max - 1));
        rB1 = __ldg(P4 + min(b1 + 32 + lane, f4max - 1));
        rB2 = __ldg(P4 + min(b1 + 64 + lane, f4max - 1));
        tile0[lane] = rA0; tile0[32 + lane] = rA1; tile0[64 + lane] = rA2;
        __syncwarp();
    }

    // ---- main loop, unrolled x2 (even: compute tile0, odd: tile1) ----
    for (int i = 0; i < niter; i += 2) {
        // EVEN: prefetch chunk(i+2)->rA, compute chunk(i) from tile0, STS rB->tile1
        {
            int cp = gw + (i + 2) * GW;
            int bp = 96 * cp;
            rA0 = __ldg(P4 + min(bp + lane,      f4max - 1));
            rA1 = __ldg(P4 + min(bp + 32 + lane, f4max - 1));
            rA2 = __ldg(P4 + min(bp + 64 + lane, f4max - 1));

            const float* sf = (const float*)tile0;
            int pb = (gw + i * GW) * CHPTS;         // chunk point base
            int p0 = pb + lane, p1 = pb + lane + 32;
            float x0 = sf[6 * lane + 0],   y0 = sf[6 * lane + 1],   z0 = sf[6 * lane + 2];
            float x1 = sf[6 * lane + 192], y1 = sf[6 * lane + 193], z1 = sf[6 * lane + 194];
            float dx = x0 - pix, dy = y0 - piy, dz = z0 - piz;
            u64 k0 = (p0 < n) ? make_key(dx * dx + dy * dy + dz * dz, p0) : 0ULL;
            dx = x1 - pix; dy = y1 - piy; dz = z1 - piz;
            u64 k1 = (p1 < n) ? make_key(dx * dx + dy * dy + dz * dz, p1) : 0ULL;
            if (__ballot_sync(FULL, umax64(k0, k1) > thresh)) {
                warp_insert(k0, mykey, thresh, lane);
                warp_insert(k1, mykey, thresh, lane);
            }

            __syncwarp();
            tile1[lane] = rB0; tile1[32 + lane] = rB1; tile1[64 + lane] = rB2;
            __syncwarp();
        }
        // ODD: prefetch chunk(i+3)->rB, compute chunk(i+1) from tile1, STS rA->tile0
        {
            int cp = gw + (i + 3) * GW;
            int bp = 96 * cp;
            rB0 = __ldg(P4 + min(bp + lane,      f4max - 1));
            rB1 = __ldg(P4 + min(bp + 32 + lane, f4max - 1));
            rB2 = __ldg(P4 + min(bp + 64 + lane, f4max - 1));

            const float* sf = (const float*)tile1;
            int pb = (gw + (i + 1) * GW) * CHPTS;
            int p0 = pb + lane, p1 = pb + lane + 32;
            float x0 = sf[6 * lane + 0],   y0 = sf[6 * lane + 1],   z0 = sf[6 * lane + 2];
            float x1 = sf[6 * lane + 192], y1 = sf[6 * lane + 193], z1 = sf[6 * lane + 194];
            float dx = x0 - pix, dy = y0 - piy, dz = z0 - piz;
            u64 k0 = (p0 < n) ? make_key(dx * dx + dy * dy + dz * dz, p0) : 0ULL;
            dx = x1 - pix; dy = y1 - piy; dz = z1 - piz;
            u64 k1 = (p1 < n) ? make_key(dx * dx + dy * dy + dz * dz, p1) : 0ULL;
            if (__ballot_sync(FULL, umax64(k0, k1) > thresh)) {
                warp_insert(k0, mykey, thresh, lane);
                warp_insert(k1, mykey, thresh, lane);
            }

            __syncwarp();
            tile0[lane] = rA0; tile0[32 + lane] = rA1; tile0[64 + lane] = rA2;
            __syncwarp();
        }
    }

    // ---- block reduce: 8 warp lists -> sorted descending top-16 ----
    __syncthreads();                       // everyone done with tile smem
    u64* sm = (u64*)smem_raw;
    u64 sk = sort16_desc((lane < 16) ? mykey : 0ULL, lane);
    if (lane < 16) sm[wid * 16 + lane] = sk;
    __syncthreads();
    #pragma unroll
    for (int nact = 4; nact >= 1; nact >>= 1) {
        u64 c = 0ULL;
        if (wid < nact) {                  // warp-uniform guard
            int id = lane & 15;
            u64 a = sm[(2 * wid) * 16 + id];
            u64 b = sm[(2 * wid + 1) * 16 + (15 - id)];
            c = clean16_desc(umax64(a, b), id);
        }
        __syncthreads();
        if (wid < nact && lane < 16) sm[wid * 16 + lane] = c;
        __syncthreads();
    }
    if (t < KTOP) g_cand[blockIdx.x * KTOP + t] = sm[t];

    // ---- last-block final merge + epilogue ----
    __shared__ int s_last;
    __threadfence();
    if (t == 0) {
        int old = atomicAdd(&g_done, 1);
        s_last = (old == NBLK - 1);
        if (s_last) g_done = 0;            // reset for next graph replay
    }
    __syncthreads();
    if (!s_last) return;
    __threadfence();

    u64* sl = (u64*)smem_raw;              // 296*16 u64
    int unit = t >> 4;                     // 16 merge units of 16 lanes
    int id = t & 15;

    // Level 1: 592 gmem lists -> 296 smem lists (unconditional shfl)
    for (int u0 = 0; u0 < 296; u0 += 16) {
        int u = u0 + unit;
        bool act = u < 296;
        int ga = act ? (2 * u) * KTOP + id : 0;
        int gb = act ? (2 * u + 1) * KTOP + (15 - id) : 0;
        u64 a = *(volatile u64*)&g_cand[ga];
        u64 b = *(volatile u64*)&g_cand[gb];
        u64 c = clean16_desc(umax64(a, b), id);   // all 256 threads execute
        if (act) sl[u * KTOP + id] = c;
    }
    __syncthreads();

    // In-place: 296 -> 148 -> 74 -> 37 -> 19 -> 10 -> 5 -> 3 -> 2 -> 1
    int mm = 296;
    while (mm > 1) {
        int h = (mm + 1) >> 1;
        for (int u0 = 0; u0 < h; u0 += 16) {
            int u = u0 + unit;
            bool act = u < h;
            int ia = act ? (2 * u) * KTOP + id : 0;
            bool hasb = act && (2 * u + 1 < mm);
            int ib = hasb ? (2 * u + 1) * KTOP + (15 - id) : 0;
            u64 a = sl[ia];
            u64 b = hasb ? sl[ib] : 0ULL;
            u64 c = clean16_desc(umax64(a, b), id);   // unconditional shfl
            __syncthreads();               // all reads before any write
            if (act) sl[u * KTOP + id] = c;
            __syncthreads();
        }
        mm = h;
    }

    if (t < KTOP) {
        u64 kk = sl[t];
        int idx = (int)(~(unsigned)(kk & 0xFFFFFFFFULL));
        float nx = P[(size_t)idx * 6 + 0];
        float ny = P[(size_t)idx * 6 + 1];
        float nz = P[(size_t)idx * 6 + 2];
        float dx = pix - nx, dy = piy - ny, dz = piz - nz;
        float dist = sqrtf(dx * dx + dy * dy + dz * dz);
        float feat[10] = {pix, piy, piz, nx, ny, nz, dx, dy, dz, dist};
        out[t * 6 + 0] = nx;
        out[t * 6 + 1] = ny;
        out[t * 6 + 2] = nz;
        #pragma unroll
        for (int j = 0; j < 3; j++) {
            float acc = bb[j];
            #pragma unroll
            for (int q = 0; q < 10; q++) acc += feat[q] * W[j * 10 + q];
            out[t * 6 + 3 + j] = acc;
        }
    }
}

extern "C" void kernel_launch(void* const* d_in, const int* in_sizes, int n_in,
                              void* d_out, int out_size) {
    const float* P  = (const float*)d_in[0];
    const float* W  = (const float*)d_in[1];
    const float* b  = (const float*)d_in[2];
    const int*   ip = (const int*)d_in[3];
    float* out = (float*)d_out;
    int n = in_sizes[0] / 6;
    int f4max = in_sizes[0] / 4;
    int nchunk = (n + CHPTS - 1) / CHPTS;
    int niter = (nchunk + GW - 1) / GW;
    niter = (niter + 1) & ~1;              // even

    locse_fused<<<NBLK, TPB>>>(P, W, b, ip, out, n, f4max, niter);
}